// round 2
// baseline (speedup 1.0000x reference)
#include <cuda_runtime.h>
#include <math.h>

#define B_    64
#define T_    512
#define EMB_  256
#define HD_   256
#define G4_   1024
#define TAGS_ 11
#define NEGV  (-10000.0f)

// ---------------- scratch (static device globals; no allocs) ----------------
__device__ float g_Gx[(long)2 * T_ * B_ * G4_];     // 268 MB: pre-projected gates
__device__ float g_Hout[(long)2 * T_ * B_ * HD_];   // 67 MB: h for all t, both dirs
__device__ float g_h[2 * 2 * B_ * HD_];             // double-buffered recurrent h
__device__ float g_feats[T_ * B_ * TAGS_];          // tag features
__device__ unsigned g_cnt = 0;
__device__ unsigned g_gen = 0;

// ---------------- software grid barrier (all CTAs co-resident) ----------------
__device__ __forceinline__ void gsync(int nb) {
    __threadfence();
    __syncthreads();
    if (threadIdx.x == 0) {
        volatile unsigned* genp = &g_gen;
        unsigned g = *genp;
        unsigned old = atomicAdd(&g_cnt, 1u);
        if (old == (unsigned)(nb - 1)) {
            atomicExch(&g_cnt, 0u);
            __threadfence();
            atomicAdd(&g_gen, 1u);
        } else {
            while (*genp == g) { }
        }
    }
    __syncthreads();
    __threadfence();
}

// =====================================================================
// K1: Gx[dir][t][b][col] = sum_k embed[sent[b][t]][k] * Wih[dir][col][k] + bias[col]
// Tiled SGEMM: 64 rows (= all b of one t) x 64 cols, K=256 in chunks of 32.
// grid: (512 row-tiles == t, 32 col-tiles), 256 threads.
// =====================================================================
__global__ void gx_kernel(const int* __restrict__ sent,
                          const float* __restrict__ embed,
                          const float* __restrict__ Wf, const float* __restrict__ bf,
                          const float* __restrict__ Wb, const float* __restrict__ bb)
{
    __shared__ __align__(16) float As[32][68];   // [k][row]
    __shared__ __align__(16) float Bs[32][68];   // [k][col]
    __shared__ int toks[64];

    const int t     = blockIdx.x;           // 0..511
    const int col0  = blockIdx.y * 64;      // 0..2047
    const int dir   = col0 >> 10;
    const int gcol0 = col0 & 1023;
    const float* __restrict__ W    = dir ? Wb : Wf;
    const float* __restrict__ bias = dir ? bb : bf;

    const int tid = threadIdx.x;
    if (tid < 64) toks[tid] = sent[tid * T_ + t];   // sentence[b][t]
    __syncthreads();

    const int rowg = tid & 15;   // rows rowg*4..+3
    const int colg = tid >> 4;   // cols colg*4..+3

    float acc[4][4];
#pragma unroll
    for (int i = 0; i < 4; i++)
#pragma unroll
        for (int j = 0; j < 4; j++) acc[i][j] = 0.f;

    for (int k0 = 0; k0 < EMB_; k0 += 32) {
#pragma unroll
        for (int i = 0; i < 2; i++) {
            int e   = tid + i * 256;     // 0..511
            int r   = e >> 3;            // 0..63
            int seg = e & 7;             // k-offset seg*4
            float4 va = *(const float4*)(embed + (long)toks[r] * EMB_ + k0 + seg * 4);
            As[seg * 4 + 0][r] = va.x; As[seg * 4 + 1][r] = va.y;
            As[seg * 4 + 2][r] = va.z; As[seg * 4 + 3][r] = va.w;
            float4 vb = *(const float4*)(W + (long)(gcol0 + r) * EMB_ + k0 + seg * 4);
            Bs[seg * 4 + 0][r] = vb.x; Bs[seg * 4 + 1][r] = vb.y;
            Bs[seg * 4 + 2][r] = vb.z; Bs[seg * 4 + 3][r] = vb.w;
        }
        __syncthreads();
#pragma unroll
        for (int k = 0; k < 32; k++) {
            float4 a  = *(float4*)&As[k][rowg * 4];
            float4 b4 = *(float4*)&Bs[k][colg * 4];
            acc[0][0] = fmaf(a.x, b4.x, acc[0][0]); acc[0][1] = fmaf(a.x, b4.y, acc[0][1]);
            acc[0][2] = fmaf(a.x, b4.z, acc[0][2]); acc[0][3] = fmaf(a.x, b4.w, acc[0][3]);
            acc[1][0] = fmaf(a.y, b4.x, acc[1][0]); acc[1][1] = fmaf(a.y, b4.y, acc[1][1]);
            acc[1][2] = fmaf(a.y, b4.z, acc[1][2]); acc[1][3] = fmaf(a.y, b4.w, acc[1][3]);
            acc[2][0] = fmaf(a.z, b4.x, acc[2][0]); acc[2][1] = fmaf(a.z, b4.y, acc[2][1]);
            acc[2][2] = fmaf(a.z, b4.z, acc[2][2]); acc[2][3] = fmaf(a.z, b4.w, acc[2][3]);
            acc[3][0] = fmaf(a.w, b4.x, acc[3][0]); acc[3][1] = fmaf(a.w, b4.y, acc[3][1]);
            acc[3][2] = fmaf(a.w, b4.z, acc[3][2]); acc[3][3] = fmaf(a.w, b4.w, acc[3][3]);
        }
        __syncthreads();
    }

    const long base = ((long)dir * T_ + t) * B_;
#pragma unroll
    for (int i = 0; i < 4; i++) {
        int b = rowg * 4 + i;
        int c = gcol0 + colg * 4;
        float4 o;
        o.x = acc[i][0] + bias[c + 0];
        o.y = acc[i][1] + bias[c + 1];
        o.z = acc[i][2] + bias[c + 2];
        o.w = acc[i][3] + bias[c + 3];
        *(float4*)(g_Gx + (base + b) * G4_ + c) = o;
    }
}

// =====================================================================
// K2: persistent bidirectional LSTM.
// 128 CTAs x 256 threads. CTA = (dir, 4 hidden units). thread = (b, u).
// Per step: stage full h (64x256) into smem, 16-col x 64-b GEMM, gate math,
// write h slice to double-buffered global, grid sync.
// dynamic smem: Wsh[16][260] + hs[64][260] = 83,200 B
// =====================================================================
#define LSTM_NB   128
#define WSTRIDE   260
#define LSTM_SMEM ((16 + 64) * WSTRIDE * 4)

__global__ void __launch_bounds__(256, 1)
lstm_kernel(const float* __restrict__ Whh_f, const float* __restrict__ Whh_b,
            const float* __restrict__ h0f, const float* __restrict__ c0f,
            const float* __restrict__ h0b, const float* __restrict__ c0b,
            const float* __restrict__ mask)
{
    extern __shared__ __align__(16) float sm[];
    float* Wsh = sm;                    // 16 rows x 260
    float* hs  = sm + 16 * WSTRIDE;     // 64 rows x 260

    const int cta = blockIdx.x;
    const int dir = cta >> 6;
    const int u0  = (cta & 63) * 4;
    const int tid = threadIdx.x;
    const int b   = tid >> 2;
    const int u   = tid & 3;

    const float* __restrict__ Whh = dir ? Whh_b : Whh_f;
    const float* __restrict__ h0  = dir ? h0b : h0f;
    const float* __restrict__ c0  = dir ? c0b : c0f;

    // preload weight slice: Wsh[q*4+uu][k] = Whh[q*256 + u0+uu][k]
#pragma unroll
    for (int i = 0; i < 4; i++) {
        int f  = tid + i * 256;        // float4 units, 0..1023
        int r  = f >> 6;               // 0..15
        int k4 = f & 63;
        int grow = (r >> 2) * HD_ + u0 + (r & 3);
        float4 w = *(const float4*)(Whh + (long)grow * HD_ + k4 * 4);
        *(float4*)&Wsh[r * WSTRIDE + k4 * 4] = w;
    }

    float c = c0[b * HD_ + u0 + u];
    float h = h0[b * HD_ + u0 + u];
    g_h[((dir * 2 + 0) * B_ + b) * HD_ + u0 + u] = h;
    gsync(LSTM_NB);

    for (int s = 0; s < T_; s++) {
        const int t = dir ? (T_ - 1 - s) : s;
        const int p = s & 1;
        const float* hin = g_h + ((dir * 2 + p) * B_) * HD_;

        // stage h into smem (padded rows: conflict-free reads)
#pragma unroll
        for (int i = 0; i < 16; i++) {
            int f  = tid + i * 256;    // float4 units, 0..4095
            int bb = f >> 6;
            int k4 = f & 63;
            float4 v = *(const float4*)(hin + bb * HD_ + k4 * 4);
            *(float4*)&hs[bb * WSTRIDE + k4 * 4] = v;
        }
        __syncthreads();

        const float* gx = g_Gx + (((long)dir * T_ + t) * B_ + b) * G4_;
        float a0 = gx[0 * HD_ + u0 + u];
        float a1 = gx[1 * HD_ + u0 + u];
        float a2 = gx[2 * HD_ + u0 + u];
        float a3 = gx[3 * HD_ + u0 + u];

        const float* hrow = &hs[b * WSTRIDE];
        const float* w0p = &Wsh[(0 + u) * WSTRIDE];
        const float* w1p = &Wsh[(4 + u) * WSTRIDE];
        const float* w2p = &Wsh[(8 + u) * WSTRIDE];
        const float* w3p = &Wsh[(12 + u) * WSTRIDE];
#pragma unroll 8
        for (int k4 = 0; k4 < 64; k4++) {
            float4 hv = *(float4*)&hrow[k4 * 4];
            float4 w0 = *(float4*)&w0p[k4 * 4];
            float4 w1 = *(float4*)&w1p[k4 * 4];
            float4 w2 = *(float4*)&w2p[k4 * 4];
            float4 w3 = *(float4*)&w3p[k4 * 4];
            a0 = fmaf(hv.x, w0.x, a0); a0 = fmaf(hv.y, w0.y, a0);
            a0 = fmaf(hv.z, w0.z, a0); a0 = fmaf(hv.w, w0.w, a0);
            a1 = fmaf(hv.x, w1.x, a1); a1 = fmaf(hv.y, w1.y, a1);
            a1 = fmaf(hv.z, w1.z, a1); a1 = fmaf(hv.w, w1.w, a1);
            a2 = fmaf(hv.x, w2.x, a2); a2 = fmaf(hv.y, w2.y, a2);
            a2 = fmaf(hv.z, w2.z, a2); a2 = fmaf(hv.w, w2.w, a2);
            a3 = fmaf(hv.x, w3.x, a3); a3 = fmaf(hv.y, w3.y, a3);
            a3 = fmaf(hv.z, w3.z, a3); a3 = fmaf(hv.w, w3.w, a3);
        }

        float si = 1.f / (1.f + expf(-a0));
        float sf = 1.f / (1.f + expf(-a1));
        float tg = tanhf(a2);
        float so = 1.f / (1.f + expf(-a3));
        float cn = sf * c + si * tg;
        float hn = so * tanhf(cn);
        float mt = mask[t * B_ + b];
        h = mt * hn + (1.f - mt) * h;
        c = mt * cn + (1.f - mt) * c;

        g_h[((dir * 2 + (1 - p)) * B_ + b) * HD_ + u0 + u] = h;
        g_Hout[(((long)dir * T_ + t) * B_ + b) * HD_ + u0 + u] = h;

        gsync(LSTM_NB);
    }
}

// =====================================================================
// K3: feats[t][b][j] = (sum_k (h[k]*m) * Wtag[j][k] + btag[j]) * m
// grid: 512 (per t), 256 threads; warp-per-batch-row, Wtag in smem.
// =====================================================================
__global__ void feats_kernel(const float* __restrict__ Wtag,
                             const float* __restrict__ btag,
                             const float* __restrict__ mask)
{
    __shared__ float Ws[TAGS_ * 512];
    __shared__ float bts[TAGS_];
    const int t   = blockIdx.x;
    const int tid = threadIdx.x;
    for (int i = tid; i < TAGS_ * 512; i += 256) Ws[i] = Wtag[i];
    if (tid < TAGS_) bts[tid] = btag[tid];
    __syncthreads();

    const int w    = tid >> 5;
    const int lane = tid & 31;
    for (int b = w; b < B_; b += 8) {
        float mt = mask[t * B_ + b];
        float acc[TAGS_];
#pragma unroll
        for (int j = 0; j < TAGS_; j++) acc[j] = 0.f;
        const float* Hf = g_Hout + (((long)0 * T_ + t) * B_ + b) * HD_;
        const float* Hb = g_Hout + (((long)1 * T_ + t) * B_ + b) * HD_;
        for (int k = lane; k < HD_; k += 32) {
            float hv  = Hf[k] * mt;
            float hv2 = Hb[k] * mt;
#pragma unroll
            for (int j = 0; j < TAGS_; j++) {
                acc[j] = fmaf(hv,  Ws[j * 512 + k],        acc[j]);
                acc[j] = fmaf(hv2, Ws[j * 512 + HD_ + k],  acc[j]);
            }
        }
#pragma unroll
        for (int j = 0; j < TAGS_; j++)
#pragma unroll
            for (int off = 16; off > 0; off >>= 1)
                acc[j] += __shfl_xor_sync(0xffffffffu, acc[j], off);
        if (lane < TAGS_)
            g_feats[(t * B_ + b) * TAGS_ + lane] = (acc[lane] + bts[lane]) * mt;
    }
}

// =====================================================================
// K4: Viterbi. 1 CTA per batch element. feats + backpointers in smem.
// Tie-break = lowest index (matches jnp.argmax).
// =====================================================================
__global__ void viterbi_kernel(const float* __restrict__ trans,
                               const float* __restrict__ mask,
                               float* __restrict__ out, int out_size)
{
    __shared__ float fsh[T_ * TAGS_];
    __shared__ unsigned char ptrs[T_ * TAGS_];
    __shared__ float trs[TAGS_ * TAGS_];
    const int b   = blockIdx.x;
    const int tid = threadIdx.x;   // 128

    for (int i = tid; i < T_ * TAGS_; i += 128) {
        int t = i / TAGS_, j = i % TAGS_;
        fsh[i] = g_feats[(t * B_ + b) * TAGS_ + j];
    }
    for (int i = tid; i < TAGS_ * TAGS_; i += 128) trs[i] = trans[i];
    __syncthreads();
    if (tid >= 32) return;

    const int j  = tid;
    const int jc = (j < TAGS_) ? j : 0;
    float score = (j == 9) ? 0.f : NEGV;   // START=9
    float trow[TAGS_];
#pragma unroll
    for (int q = 0; q < TAGS_; q++) trow[q] = trs[jc * TAGS_ + q];

    for (int t = 0; t < T_; t++) {
        float best = -1e30f;
        int arg = 0;
#pragma unroll
        for (int q = 0; q < TAGS_; q++) {
            float sq = __shfl_sync(0xffffffffu, score, q);
            float v = sq + trow[q];
            if (v > best) { best = v; arg = q; }
        }
        float mt = mask[t * B_ + b];
        float ns = best + fsh[t * TAGS_ + jc];
        if (j < TAGS_) {
            ptrs[t * TAGS_ + j] = (unsigned char)arg;
            if (mt > 0.f) score = ns;
        }
    }

    float fin = score + trs[10 * TAGS_ + jc];   // STOP=10
    float bs = -1e30f;
    int bt = 0;
#pragma unroll
    for (int q = 0; q < TAGS_; q++) {
        float v = __shfl_sync(0xffffffffu, fin, q);
        if (v > bs) { bs = v; bt = q; }
    }

    if (tid == 0) {
        if (out_size >= B_ * T_ + B_) out[B_ * T_ + b] = bs;
        int cur = bt;
        for (int t = T_ - 1; t >= 0; t--) {
            if (b * T_ + t < out_size) out[b * T_ + t] = (float)cur;
            cur = ptrs[t * TAGS_ + cur];
        }
    }
}

// =====================================================================
extern "C" void kernel_launch(void* const* d_in, const int* in_sizes, int n_in,
                              void* d_out, int out_size)
{
    const int*   sent  = (const int*)d_in[0];
    const float* mask  = (const float*)d_in[1];
    const float* embed = (const float*)d_in[2];
    const float* Wih_f = (const float*)d_in[3];
    const float* Whh_f = (const float*)d_in[4];
    const float* b_f   = (const float*)d_in[5];
    const float* Wih_b = (const float*)d_in[6];
    const float* Whh_b = (const float*)d_in[7];
    const float* b_b   = (const float*)d_in[8];
    const float* h0f   = (const float*)d_in[9];
    const float* c0f   = (const float*)d_in[10];
    const float* h0b   = (const float*)d_in[11];
    const float* c0b   = (const float*)d_in[12];
    const float* Wtag  = (const float*)d_in[13];
    const float* btag  = (const float*)d_in[14];
    const float* trans = (const float*)d_in[15];

    gx_kernel<<<dim3(T_, 32), 256>>>(sent, embed, Wih_f, b_f, Wih_b, b_b);

    cudaFuncSetAttribute(lstm_kernel, cudaFuncAttributeMaxDynamicSharedMemorySize, LSTM_SMEM);
    lstm_kernel<<<LSTM_NB, 256, LSTM_SMEM>>>(Whh_f, Whh_b, h0f, c0f, h0b, c0b, mask);

    feats_kernel<<<T_, 256>>>(Wtag, btag, mask);

    viterbi_kernel<<<B_, 128>>>(trans, mask, (float*)d_out, out_size);
}

// round 3
// speedup vs baseline: 1.0718x; 1.0718x over previous
#include <cuda_runtime.h>
#include <math.h>

#define B_    64
#define T_    512
#define EMB_  256
#define HD_   256
#define G4_   1024
#define TAGS_ 11
#define NEGV  (-10000.0f)
#define GSTRIDE (256 * 64)   // gate stride in g_Gx elements

// ---------------- scratch (static device globals; no allocs) ----------------
__device__ float g_Gx[(long)2 * T_ * B_ * G4_];     // [dir][t][gate][unit][b]
__device__ float g_Hout[(long)2 * T_ * B_ * HD_];   // [dir][t][b][unit]
__device__ float g_h[2 * 2 * B_ * HD_];             // double-buffered recurrent h
__device__ float g_feats[T_ * B_ * TAGS_];
#define LSTM_NB 128
__device__ unsigned g_flags[LSTM_NB];               // monotonic epochs across launches

// ---------------- packed f32x2 helpers ----------------
__device__ __forceinline__ void ffma2(unsigned long long& d,
                                      unsigned long long a,
                                      unsigned long long b) {
    asm("fma.rn.f32x2 %0, %1, %2, %0;" : "+l"(d) : "l"(a), "l"(b));
}
__device__ __forceinline__ float2 upk(unsigned long long v) {
    float2 f; asm("mov.b64 {%0, %1}, %2;" : "=f"(f.x), "=f"(f.y) : "l"(v)); return f;
}

// ---------------- flag-array grid barrier ----------------
__device__ __forceinline__ void g_arrive(unsigned base, unsigned val) {
    __syncthreads();
    if (threadIdx.x == 0) {
        __threadfence();
        *((volatile unsigned*)&g_flags[blockIdx.x]) = base + val;
    }
}
__device__ __forceinline__ void g_wait(unsigned base, unsigned val) {
    if (threadIdx.x < LSTM_NB) {
        volatile unsigned* f = g_flags;
        while ((int)(f[threadIdx.x] - base) < (int)val) { }
    }
    __syncthreads();
}

// =====================================================================
// K1: Gx = embed[sent] @ Wih.T + b, written as [dir][t][gate][unit][b].
// Tile: 64 rows (batch) x 128 cols, K=256 in chunks of 32. f32x2 FMAs.
// grid (512, 16): x = t, y = dir*8 + coltile. 256 threads.
// Thread tile: 8 rows (rowg + 8i) x 4 cols (colg*4+j).
// =====================================================================
__global__ void gx_kernel(const int* __restrict__ sent,
                          const float* __restrict__ embed,
                          const float* __restrict__ Wf, const float* __restrict__ bf,
                          const float* __restrict__ Wb, const float* __restrict__ bb)
{
    __shared__ __align__(16) float As[64 * 36];    // [row][k] row-major, stride 36
    __shared__ __align__(16) float Bs[128 * 36];   // [col][k]
    __shared__ int toks[64];

    const int t     = blockIdx.x;
    const int dir   = blockIdx.y >> 3;
    const int gcol0 = (blockIdx.y & 7) * 128;
    const float* __restrict__ W    = dir ? Wb : Wf;
    const float* __restrict__ bias = dir ? bb : bf;

    const int tid = threadIdx.x;
    if (tid < 64) toks[tid] = sent[tid * T_ + t];
    __syncthreads();

    const int rowg = tid & 7;    // rows rowg + 8i
    const int colg = tid >> 3;   // cols colg*4 + j

    unsigned long long acc[8][4];
#pragma unroll
    for (int i = 0; i < 8; i++)
#pragma unroll
        for (int j = 0; j < 4; j++) acc[i][j] = 0ull;

    for (int k0 = 0; k0 < EMB_; k0 += 32) {
#pragma unroll
        for (int i = 0; i < 2; i++) {
            int e = tid + i * 256, r = e >> 3, seg = e & 7;
            float4 va = *(const float4*)(embed + (long)toks[r] * EMB_ + k0 + seg * 4);
            *(float4*)&As[r * 36 + seg * 4] = va;
        }
#pragma unroll
        for (int i = 0; i < 4; i++) {
            int e = tid + i * 256, r = e >> 3, seg = e & 7;
            float4 vb = *(const float4*)(W + (long)(gcol0 + r) * EMB_ + k0 + seg * 4);
            *(float4*)&Bs[r * 36 + seg * 4] = vb;
        }
        __syncthreads();
#pragma unroll
        for (int k4 = 0; k4 < 8; k4++) {
            ulonglong2 bv[4];
#pragma unroll
            for (int j = 0; j < 4; j++)
                bv[j] = *(const ulonglong2*)&Bs[(colg * 4 + j) * 36 + k4 * 4];
#pragma unroll
            for (int i = 0; i < 8; i++) {
                ulonglong2 av = *(const ulonglong2*)&As[(rowg + 8 * i) * 36 + k4 * 4];
#pragma unroll
                for (int j = 0; j < 4; j++) {
                    ffma2(acc[i][j], av.x, bv[j].x);
                    ffma2(acc[i][j], av.y, bv[j].y);
                }
            }
        }
        __syncthreads();
    }

    const long tb = (long)dir * T_ + t;
#pragma unroll
    for (int j = 0; j < 4; j++) {
        int col = gcol0 + colg * 4 + j;      // 0..1023
        float bsv = bias[col];
        long obase = ((tb * 4 + (col >> 8)) * 256 + (col & 255)) * 64;
#pragma unroll
        for (int i = 0; i < 8; i++) {
            float2 p = upk(acc[i][j]);
            g_Gx[obase + rowg + 8 * i] = p.x + p.y + bsv;
        }
    }
}

// =====================================================================
// K2: persistent bidirectional LSTM, 128 CTAs x 256 threads.
// CTA = (dir, 4 units). thread: b = tid&63, u = tid>>6 (coalesced Gx/mask).
// f32x2 packed dot products; flag-array grid barrier; L2-coherent h exchange.
// =====================================================================
#define WSTRIDE   260
#define LSTM_SMEM ((16 + 64) * WSTRIDE * 4)

__global__ void __launch_bounds__(256, 1)
lstm_kernel(const float* __restrict__ Whh_f, const float* __restrict__ Whh_b,
            const float* __restrict__ h0f, const float* __restrict__ c0f,
            const float* __restrict__ h0b, const float* __restrict__ c0b,
            const float* __restrict__ mask)
{
    extern __shared__ __align__(16) float sm[];
    float* Wsh = sm;                    // 16 rows x 260: row g*4+u = Whh[g*256+unit]
    float* hs  = sm + 16 * WSTRIDE;     // 64 rows x 260

    const int cta = blockIdx.x;
    const int dir = cta >> 6;
    const int u0  = (cta & 63) * 4;
    const int tid = threadIdx.x;
    const int b    = tid & 63;
    const int u    = tid >> 6;
    const int unit = u0 + u;

    const float* __restrict__ Whh = dir ? Whh_b : Whh_f;
    const float* __restrict__ h0  = dir ? h0b : h0f;
    const float* __restrict__ c0  = dir ? c0b : c0f;

    __shared__ unsigned sbase;
    if (tid == 0) sbase = *((volatile unsigned*)&g_flags[cta]);
    __syncthreads();
    const unsigned base = sbase;

    // preload weight slice
#pragma unroll
    for (int i = 0; i < 4; i++) {
        int f  = tid + i * 256;        // float4 units 0..1023
        int r  = f >> 6;               // 0..15
        int k4 = f & 63;
        int grow = (r >> 2) * HD_ + u0 + (r & 3);
        float4 w = *(const float4*)(Whh + (long)grow * HD_ + k4 * 4);
        *(float4*)&Wsh[r * WSTRIDE + k4 * 4] = w;
    }

    float c = c0[b * HD_ + unit];
    float h = h0[b * HD_ + unit];
    __stcg(&g_h[((dir * 2 + 0) * B_ + b) * HD_ + unit], h);
    g_arrive(base, 1);

    const float* w0p = &Wsh[(0 + u) * WSTRIDE];
    const float* w1p = &Wsh[(4 + u) * WSTRIDE];
    const float* w2p = &Wsh[(8 + u) * WSTRIDE];
    const float* w3p = &Wsh[(12 + u) * WSTRIDE];
    const float* hrow = &hs[b * WSTRIDE];

    for (int s = 0; s < T_; s++) {
        const int t = dir ? (T_ - 1 - s) : s;
        const int p = s & 1;

        // prefetch gate pre-activations + mask (independent of barrier)
        const float* gx = g_Gx + (((long)dir * T_ + t) * 4 * 256 + unit) * 64 + b;
        float ga0 = __ldg(gx);
        float ga1 = __ldg(gx + GSTRIDE);
        float ga2 = __ldg(gx + 2 * GSTRIDE);
        float ga3 = __ldg(gx + 3 * GSTRIDE);
        float mt  = __ldg(mask + t * B_ + b);

        g_wait(base, s + 1);

        // stage h into smem (L2-coherent reads)
        const float* hin = g_h + ((dir * 2 + p) * B_) * HD_;
#pragma unroll
        for (int i = 0; i < 16; i++) {
            int f  = tid + i * 256;
            int bb = f >> 6;
            int k4 = f & 63;
            float4 v = __ldcg((const float4*)(hin + bb * HD_ + k4 * 4));
            *(float4*)&hs[bb * WSTRIDE + k4 * 4] = v;
        }
        __syncthreads();

        unsigned long long a0p = 0ull, a1p = 0ull, a2p = 0ull, a3p = 0ull;
#pragma unroll 8
        for (int k4 = 0; k4 < 64; k4++) {
            ulonglong2 hv = *(const ulonglong2*)&hrow[k4 * 4];
            ulonglong2 w0 = *(const ulonglong2*)&w0p[k4 * 4];
            ulonglong2 w1 = *(const ulonglong2*)&w1p[k4 * 4];
            ulonglong2 w2 = *(const ulonglong2*)&w2p[k4 * 4];
            ulonglong2 w3 = *(const ulonglong2*)&w3p[k4 * 4];
            ffma2(a0p, hv.x, w0.x); ffma2(a0p, hv.y, w0.y);
            ffma2(a1p, hv.x, w1.x); ffma2(a1p, hv.y, w1.y);
            ffma2(a2p, hv.x, w2.x); ffma2(a2p, hv.y, w2.y);
            ffma2(a3p, hv.x, w3.x); ffma2(a3p, hv.y, w3.y);
        }
        float2 q0 = upk(a0p), q1 = upk(a1p), q2 = upk(a2p), q3 = upk(a3p);
        float a0 = ga0 + q0.x + q0.y;
        float a1 = ga1 + q1.x + q1.y;
        float a2 = ga2 + q2.x + q2.y;
        float a3 = ga3 + q3.x + q3.y;

        float si = 1.f / (1.f + expf(-a0));
        float sf = 1.f / (1.f + expf(-a1));
        float tg = tanhf(a2);
        float so = 1.f / (1.f + expf(-a3));
        float cn = sf * c + si * tg;
        float hn = so * tanhf(cn);
        h = mt * hn + (1.f - mt) * h;
        c = mt * cn + (1.f - mt) * c;

        __stcg(&g_h[((dir * 2 + (1 - p)) * B_ + b) * HD_ + unit], h);
        g_Hout[(((long)dir * T_ + t) * B_ + b) * HD_ + unit] = h;

        g_arrive(base, s + 2);
    }
}

// =====================================================================
// K3: feats[t][b][j] = (sum_k (h[k]*m) * Wtag[j][k] + btag[j]) * m
// =====================================================================
__global__ void feats_kernel(const float* __restrict__ Wtag,
                             const float* __restrict__ btag,
                             const float* __restrict__ mask)
{
    __shared__ float Ws[TAGS_ * 512];
    __shared__ float bts[TAGS_];
    const int t   = blockIdx.x;
    const int tid = threadIdx.x;
    for (int i = tid; i < TAGS_ * 512; i += 256) Ws[i] = Wtag[i];
    if (tid < TAGS_) bts[tid] = btag[tid];
    __syncthreads();

    const int w    = tid >> 5;
    const int lane = tid & 31;
    for (int b = w; b < B_; b += 8) {
        float mt = mask[t * B_ + b];
        float acc[TAGS_];
#pragma unroll
        for (int j = 0; j < TAGS_; j++) acc[j] = 0.f;
        const float* Hf = g_Hout + (((long)0 * T_ + t) * B_ + b) * HD_;
        const float* Hb = g_Hout + (((long)1 * T_ + t) * B_ + b) * HD_;
        for (int k = lane; k < HD_; k += 32) {
            float hv  = Hf[k] * mt;
            float hv2 = Hb[k] * mt;
#pragma unroll
            for (int j = 0; j < TAGS_; j++) {
                acc[j] = fmaf(hv,  Ws[j * 512 + k],       acc[j]);
                acc[j] = fmaf(hv2, Ws[j * 512 + HD_ + k], acc[j]);
            }
        }
#pragma unroll
        for (int j = 0; j < TAGS_; j++)
#pragma unroll
            for (int off = 16; off > 0; off >>= 1)
                acc[j] += __shfl_xor_sync(0xffffffffu, acc[j], off);
        if (lane < TAGS_)
            g_feats[(t * B_ + b) * TAGS_ + lane] = (acc[lane] + bts[lane]) * mt;
    }
}

// =====================================================================
// K4: Viterbi. 1 CTA per batch element; feats + mask + ptrs in smem.
// =====================================================================
__global__ void viterbi_kernel(const float* __restrict__ trans,
                               const float* __restrict__ mask,
                               float* __restrict__ out, int out_size)
{
    __shared__ float fsh[T_ * TAGS_];
    __shared__ float msh[T_];
    __shared__ unsigned char ptrs[T_ * TAGS_];
    __shared__ float trs[TAGS_ * TAGS_];
    const int b   = blockIdx.x;
    const int tid = threadIdx.x;   // 128

    for (int i = tid; i < T_ * TAGS_; i += 128) {
        int t = i / TAGS_, j = i % TAGS_;
        fsh[i] = g_feats[(t * B_ + b) * TAGS_ + j];
    }
    for (int i = tid; i < T_; i += 128) msh[i] = mask[i * B_ + b];
    for (int i = tid; i < TAGS_ * TAGS_; i += 128) trs[i] = trans[i];
    __syncthreads();
    if (tid >= 32) return;

    const int j  = tid;
    const int jc = (j < TAGS_) ? j : 0;
    float score = (j == 9) ? 0.f : NEGV;   // START=9
    float trow[TAGS_];
#pragma unroll
    for (int q = 0; q < TAGS_; q++) trow[q] = trs[jc * TAGS_ + q];

    for (int t = 0; t < T_; t++) {
        float best = -1e30f;
        int arg = 0;
#pragma unroll
        for (int q = 0; q < TAGS_; q++) {
            float sq = __shfl_sync(0xffffffffu, score, q);
            float v = sq + trow[q];
            if (v > best) { best = v; arg = q; }
        }
        float mt = msh[t];
        float ns = best + fsh[t * TAGS_ + jc];
        if (j < TAGS_) {
            ptrs[t * TAGS_ + j] = (unsigned char)arg;
            if (mt > 0.f) score = ns;
        }
    }

    float fin = score + trs[10 * TAGS_ + jc];   // STOP=10
    float bs = -1e30f;
    int bt = 0;
#pragma unroll
    for (int q = 0; q < TAGS_; q++) {
        float v = __shfl_sync(0xffffffffu, fin, q);
        if (v > bs) { bs = v; bt = q; }
    }

    if (tid == 0) {
        if (out_size >= B_ * T_ + B_) out[B_ * T_ + b] = bs;
        int cur = bt;
        for (int t = T_ - 1; t >= 0; t--) {
            if (b * T_ + t < out_size) out[b * T_ + t] = (float)cur;
            cur = ptrs[t * TAGS_ + cur];
        }
    }
}

// =====================================================================
extern "C" void kernel_launch(void* const* d_in, const int* in_sizes, int n_in,
                              void* d_out, int out_size)
{
    const int*   sent  = (const int*)d_in[0];
    const float* mask  = (const float*)d_in[1];
    const float* embed = (const float*)d_in[2];
    const float* Wih_f = (const float*)d_in[3];
    const float* Whh_f = (const float*)d_in[4];
    const float* b_f   = (const float*)d_in[5];
    const float* Wih_b = (const float*)d_in[6];
    const float* Whh_b = (const float*)d_in[7];
    const float* b_b   = (const float*)d_in[8];
    const float* h0f   = (const float*)d_in[9];
    const float* c0f   = (const float*)d_in[10];
    const float* h0b   = (const float*)d_in[11];
    const float* c0b   = (const float*)d_in[12];
    const float* Wtag  = (const float*)d_in[13];
    const float* btag  = (const float*)d_in[14];
    const float* trans = (const float*)d_in[15];

    gx_kernel<<<dim3(T_, 16), 256>>>(sent, embed, Wih_f, b_f, Wih_b, b_b);

    cudaFuncSetAttribute(lstm_kernel, cudaFuncAttributeMaxDynamicSharedMemorySize, LSTM_SMEM);
    lstm_kernel<<<LSTM_NB, 256, LSTM_SMEM>>>(Whh_f, Whh_b, h0f, c0f, h0b, c0b, mask);

    feats_kernel<<<T_, 256>>>(Wtag, btag, mask);

    viterbi_kernel<<<B_, 128>>>(trans, mask, (float*)d_out, out_size);
}

// round 4
// speedup vs baseline: 1.1304x; 1.0547x over previous
#include <cuda_runtime.h>
#include <math.h>

#define B_    64
#define T_    512
#define EMB_  256
#define HD_   256
#define G4_   1024
#define TAGS_ 11
#define NEGV  (-10000.0f)
#define GSTRIDE (256 * 64)   // gate stride in g_Gx elements

// ---------------- scratch (static device globals; no allocs) ----------------
__device__ float g_Gx[(long)2 * T_ * B_ * G4_];              // [dir][t][gate][unit][b]
__device__ __align__(16) float g_Hout[(long)2 * T_ * B_ * HD_]; // [dir][t][unit][b]
__device__ __align__(16) float g_hbuf[2 * 2 * B_ * HD_];        // [dir][buf][unit][b] (float4-coalesced)
__device__ float g_feats[T_ * B_ * TAGS_];
#define LSTM_NB 128
__device__ unsigned g_flags[LSTM_NB];   // monotonic epochs across graph replays

// ---------------- packed f32x2 helpers ----------------
__device__ __forceinline__ void ffma2(unsigned long long& d,
                                      unsigned long long a,
                                      unsigned long long b) {
    asm("fma.rn.f32x2 %0, %1, %2, %0;" : "+l"(d) : "l"(a), "l"(b));
}
__device__ __forceinline__ float2 upk(unsigned long long v) {
    float2 f; asm("mov.b64 {%0, %1}, %2;" : "=f"(f.x), "=f"(f.y) : "l"(v)); return f;
}

// ---------------- release/acquire flag ops ----------------
__device__ __forceinline__ unsigned ld_acq(const unsigned* p) {
    unsigned v;
    asm volatile("ld.global.acquire.gpu.u32 %0, [%1];" : "=r"(v) : "l"(p));
    return v;
}
__device__ __forceinline__ void st_rel(unsigned* p, unsigned v) {
    asm volatile("st.global.release.gpu.u32 [%0], %1;" :: "l"(p), "r"(v) : "memory");
}

// =====================================================================
// K1: Gx = embed[sent] @ Wih.T + b, written as [dir][t][gate][unit][b].
// =====================================================================
__global__ void gx_kernel(const int* __restrict__ sent,
                          const float* __restrict__ embed,
                          const float* __restrict__ Wf, const float* __restrict__ bf,
                          const float* __restrict__ Wb, const float* __restrict__ bb)
{
    __shared__ __align__(16) float As[64 * 36];    // [row][k]
    __shared__ __align__(16) float Bs[128 * 36];   // [col][k]
    __shared__ int toks[64];

    const int t     = blockIdx.x;
    const int dir   = blockIdx.y >> 3;
    const int gcol0 = (blockIdx.y & 7) * 128;
    const float* __restrict__ W    = dir ? Wb : Wf;
    const float* __restrict__ bias = dir ? bb : bf;

    const int tid = threadIdx.x;
    if (tid < 64) toks[tid] = sent[tid * T_ + t];
    __syncthreads();

    const int rowg = tid & 7;
    const int colg = tid >> 3;

    unsigned long long acc[8][4];
#pragma unroll
    for (int i = 0; i < 8; i++)
#pragma unroll
        for (int j = 0; j < 4; j++) acc[i][j] = 0ull;

    for (int k0 = 0; k0 < EMB_; k0 += 32) {
#pragma unroll
        for (int i = 0; i < 2; i++) {
            int e = tid + i * 256, r = e >> 3, seg = e & 7;
            float4 va = *(const float4*)(embed + (long)toks[r] * EMB_ + k0 + seg * 4);
            *(float4*)&As[r * 36 + seg * 4] = va;
        }
#pragma unroll
        for (int i = 0; i < 4; i++) {
            int e = tid + i * 256, r = e >> 3, seg = e & 7;
            float4 vb = *(const float4*)(W + (long)(gcol0 + r) * EMB_ + k0 + seg * 4);
            *(float4*)&Bs[r * 36 + seg * 4] = vb;
        }
        __syncthreads();
#pragma unroll
        for (int k4 = 0; k4 < 8; k4++) {
            ulonglong2 bv[4];
#pragma unroll
            for (int j = 0; j < 4; j++)
                bv[j] = *(const ulonglong2*)&Bs[(colg * 4 + j) * 36 + k4 * 4];
#pragma unroll
            for (int i = 0; i < 8; i++) {
                ulonglong2 av = *(const ulonglong2*)&As[(rowg + 8 * i) * 36 + k4 * 4];
#pragma unroll
                for (int j = 0; j < 4; j++) {
                    ffma2(acc[i][j], av.x, bv[j].x);
                    ffma2(acc[i][j], av.y, bv[j].y);
                }
            }
        }
        __syncthreads();
    }

    const long tb = (long)dir * T_ + t;
#pragma unroll
    for (int j = 0; j < 4; j++) {
        int col = gcol0 + colg * 4 + j;
        float bsv = bias[col];
        long obase = ((tb * 4 + (col >> 8)) * 256 + (col & 255)) * 64;
#pragma unroll
        for (int i = 0; i < 8; i++) {
            float2 p = upk(acc[i][j]);
            g_Gx[obase + rowg + 8 * i] = p.x + p.y + bsv;
        }
    }
}

// =====================================================================
// K2: persistent bidirectional LSTM, 128 CTAs x 256 threads.
// CTA = (dir, kq = 4-unit group). thread: b = tid&63, u = tid>>6.
// h exchanged through g_hbuf in [unit][b] float4 layout (fully coalesced),
// release/acquire flag barrier split per direction, Hout off critical path.
// dyn smem: Wsh 16x260 + hs4 64KB + sh_h 256 floats
// =====================================================================
#define WSTRIDE   260
#define SM_WSH    0
#define SM_HS4    (16 * WSTRIDE)                 // float offset (16640B, 16B-aligned)
#define SM_SHH    (SM_HS4 + 64 * 64 * 4)
#define LSTM_SMEM ((SM_SHH + 256) * 4)

__global__ void __launch_bounds__(256, 1)
lstm_kernel(const float* __restrict__ Whh_f, const float* __restrict__ Whh_b,
            const float* __restrict__ h0f, const float* __restrict__ c0f,
            const float* __restrict__ h0b, const float* __restrict__ c0b,
            const float* __restrict__ mask)
{
    extern __shared__ __align__(16) float sm[];
    float*  Wsh  = sm + SM_WSH;
    float4* hs4  = (float4*)(sm + SM_HS4);       // [kq][b], same layout as g_hbuf
    float*  sh_h = sm + SM_SHH;

    const int cta = blockIdx.x;
    const int dir = cta >> 6;
    const int kq  = cta & 63;                    // unit group: units 4kq..4kq+3
    const int u0  = kq * 4;
    const int tid = threadIdx.x;
    const int b    = tid & 63;
    const int u    = tid >> 6;
    const int unit = u0 + u;

    const float* __restrict__ Whh = dir ? Whh_b : Whh_f;
    const float* __restrict__ h0  = dir ? h0b : h0f;
    const float* __restrict__ c0  = dir ? c0b : c0f;

    float4* hbuf0 = ((float4*)g_hbuf) + (dir * 2 + 0) * (64 * 64);
    float4* hbuf1 = ((float4*)g_hbuf) + (dir * 2 + 1) * (64 * 64);
    float4* HoutD = ((float4*)g_Hout) + (long)dir * T_ * 64 * 64;
    unsigned* myflag = &g_flags[cta];
    const unsigned* dflags = &g_flags[dir * 64];

    __shared__ unsigned sbase;
    if (tid == 0) sbase = ld_acq(myflag);
    __syncthreads();
    const unsigned base = sbase;

    // preload weight slice: Wsh[g*4+uu][k] = Whh[g*256 + u0+uu][k]
#pragma unroll
    for (int i = 0; i < 4; i++) {
        int f  = tid + i * 256;
        int r  = f >> 6;
        int k4 = f & 63;
        int grow = (r >> 2) * HD_ + u0 + (r & 3);
        float4 w = *(const float4*)(Whh + (long)grow * HD_ + k4 * 4);
        *(float4*)&Wsh[r * WSTRIDE + k4 * 4] = w;
    }

    float c = c0[b * HD_ + unit];
    float h = h0[b * HD_ + unit];

    // publish initial h (coalesced float4 path)
    sh_h[u * 64 + b] = h;
    __syncthreads();
    if (tid < 64) {
        float4 v = make_float4(sh_h[tid], sh_h[64 + tid], sh_h[128 + tid], sh_h[192 + tid]);
        __stcg(&hbuf0[kq * 64 + tid], v);
    }
    __syncthreads();
    if (tid == 0) st_rel(myflag, base + 1);

    const float* w0p = &Wsh[(0 + u) * WSTRIDE];
    const float* w1p = &Wsh[(4 + u) * WSTRIDE];
    const float* w2p = &Wsh[(8 + u) * WSTRIDE];
    const float* w3p = &Wsh[(12 + u) * WSTRIDE];

    for (int s = 0; s < T_; s++) {
        const int t = dir ? (T_ - 1 - s) : s;
        const int p = s & 1;

        // prefetch gate pre-activations + mask (independent of barrier)
        const float* gx = g_Gx + (((long)dir * T_ + t) * 4 * 256 + unit) * 64 + b;
        float ga0 = __ldg(gx);
        float ga1 = __ldg(gx + GSTRIDE);
        float ga2 = __ldg(gx + 2 * GSTRIDE);
        float ga3 = __ldg(gx + 3 * GSTRIDE);
        float mt  = __ldg(mask + t * B_ + b);

        // wait for all 64 CTAs of this direction
        if (tid < 64) {
            const unsigned* f = dflags + tid;
            while ((int)(ld_acq(f) - base) < (int)(s + 1)) { }
        }
        __syncthreads();

        // stage h: linear coalesced float4 copy, layouts identical
        const float4* hin = p ? hbuf1 : hbuf0;
#pragma unroll
        for (int i = 0; i < 16; i++) {
            int e = tid + i * 256;
            hs4[e] = __ldcg(hin + e);
        }
        __syncthreads();

        unsigned long long a0p = 0ull, a1p = 0ull, a2p = 0ull, a3p = 0ull;
#pragma unroll 8
        for (int q = 0; q < 64; q++) {
            ulonglong2 hv = ((const ulonglong2*)hs4)[q * 64 + b];
            ulonglong2 w0 = *(const ulonglong2*)&w0p[q * 4];
            ulonglong2 w1 = *(const ulonglong2*)&w1p[q * 4];
            ulonglong2 w2 = *(const ulonglong2*)&w2p[q * 4];
            ulonglong2 w3 = *(const ulonglong2*)&w3p[q * 4];
            ffma2(a0p, hv.x, w0.x); ffma2(a0p, hv.y, w0.y);
            ffma2(a1p, hv.x, w1.x); ffma2(a1p, hv.y, w1.y);
            ffma2(a2p, hv.x, w2.x); ffma2(a2p, hv.y, w2.y);
            ffma2(a3p, hv.x, w3.x); ffma2(a3p, hv.y, w3.y);
        }
        float2 q0 = upk(a0p), q1 = upk(a1p), q2 = upk(a2p), q3 = upk(a3p);
        float a0 = ga0 + q0.x + q0.y;
        float a1 = ga1 + q1.x + q1.y;
        float a2 = ga2 + q2.x + q2.y;
        float a3 = ga3 + q3.x + q3.y;

        float si = 1.f / (1.f + expf(-a0));
        float sf = 1.f / (1.f + expf(-a1));
        float tg = tanhf(a2);
        float so = 1.f / (1.f + expf(-a3));
        float cn = sf * c + si * tg;
        float hn = so * tanhf(cn);
        h = mt * hn + (1.f - mt) * h;
        c = mt * cn + (1.f - mt) * c;

        // publish h via coalesced float4 path
        sh_h[u * 64 + b] = h;
        __syncthreads();
        float4 v;
        if (tid < 64) {
            v = make_float4(sh_h[tid], sh_h[64 + tid], sh_h[128 + tid], sh_h[192 + tid]);
            __stcg(&((p ? hbuf0 : hbuf1)[kq * 64 + tid]), v);
        }
        __syncthreads();
        if (tid == 0) st_rel(myflag, base + s + 2);

        // Hout store AFTER the flag — off the critical path
        if (tid < 64)
            HoutD[((long)t * 64 + kq) * 64 + tid] = v;
    }
}

// =====================================================================
// K3: feats[t][b][j] = (sum_k (h[k]*m) * Wtag[j][k] + btag[j]) * m
// g_Hout layout is [dir][t][unit][b]; reads L1-cache-friendly within a block.
// =====================================================================
__global__ void feats_kernel(const float* __restrict__ Wtag,
                             const float* __restrict__ btag,
                             const float* __restrict__ mask)
{
    __shared__ float Ws[TAGS_ * 512];
    __shared__ float bts[TAGS_];
    const int t   = blockIdx.x;
    const int tid = threadIdx.x;
    for (int i = tid; i < TAGS_ * 512; i += 256) Ws[i] = Wtag[i];
    if (tid < TAGS_) bts[tid] = btag[tid];
    __syncthreads();

    const int w    = tid >> 5;
    const int lane = tid & 31;
    const float* Hf = g_Hout + ((long)t * 256) * 64;                 // dir 0
    const float* Hb = g_Hout + ((long)T_ * 256 + (long)t * 256) * 64; // dir 1
    for (int b = w; b < B_; b += 8) {
        float mt = mask[t * B_ + b];
        float acc[TAGS_];
#pragma unroll
        for (int j = 0; j < TAGS_; j++) acc[j] = 0.f;
        for (int k = lane; k < HD_; k += 32) {
            float hv  = Hf[k * 64 + b] * mt;
            float hv2 = Hb[k * 64 + b] * mt;
#pragma unroll
            for (int j = 0; j < TAGS_; j++) {
                acc[j] = fmaf(hv,  Ws[j * 512 + k],       acc[j]);
                acc[j] = fmaf(hv2, Ws[j * 512 + HD_ + k], acc[j]);
            }
        }
#pragma unroll
        for (int j = 0; j < TAGS_; j++)
#pragma unroll
            for (int off = 16; off > 0; off >>= 1)
                acc[j] += __shfl_xor_sync(0xffffffffu, acc[j], off);
        if (lane < TAGS_)
            g_feats[(t * B_ + b) * TAGS_ + lane] = (acc[lane] + bts[lane]) * mt;
    }
}

// =====================================================================
// K4: Viterbi. 1 CTA per batch element; feats + mask + ptrs in smem.
// =====================================================================
__global__ void viterbi_kernel(const float* __restrict__ trans,
                               const float* __restrict__ mask,
                               float* __restrict__ out, int out_size)
{
    __shared__ float fsh[T_ * TAGS_];
    __shared__ float msh[T_];
    __shared__ unsigned char ptrs[T_ * TAGS_];
    __shared__ float trs[TAGS_ * TAGS_];
    const int b   = blockIdx.x;
    const int tid = threadIdx.x;   // 128

    for (int i = tid; i < T_ * TAGS_; i += 128) {
        int t = i / TAGS_, j = i % TAGS_;
        fsh[i] = g_feats[(t * B_ + b) * TAGS_ + j];
    }
    for (int i = tid; i < T_; i += 128) msh[i] = mask[i * B_ + b];
    for (int i = tid; i < TAGS_ * TAGS_; i += 128) trs[i] = trans[i];
    __syncthreads();
    if (tid >= 32) return;

    const int j  = tid;
    const int jc = (j < TAGS_) ? j : 0;
    float score = (j == 9) ? 0.f : NEGV;   // START=9
    float trow[TAGS_];
#pragma unroll
    for (int q = 0; q < TAGS_; q++) trow[q] = trs[jc * TAGS_ + q];

    for (int t = 0; t < T_; t++) {
        float best = -1e30f;
        int arg = 0;
#pragma unroll
        for (int q = 0; q < TAGS_; q++) {
            float sq = __shfl_sync(0xffffffffu, score, q);
            float v = sq + trow[q];
            if (v > best) { best = v; arg = q; }
        }
        float mt = msh[t];
        float ns = best + fsh[t * TAGS_ + jc];
        if (j < TAGS_) {
            ptrs[t * TAGS_ + j] = (unsigned char)arg;
            if (mt > 0.f) score = ns;
        }
    }

    float fin = score + trs[10 * TAGS_ + jc];   // STOP=10
    float bs = -1e30f;
    int bt = 0;
#pragma unroll
    for (int q = 0; q < TAGS_; q++) {
        float v = __shfl_sync(0xffffffffu, fin, q);
        if (v > bs) { bs = v; bt = q; }
    }

    if (tid == 0) {
        if (out_size >= B_ * T_ + B_) out[B_ * T_ + b] = bs;
        int cur = bt;
        for (int t = T_ - 1; t >= 0; t--) {
            if (b * T_ + t < out_size) out[b * T_ + t] = (float)cur;
            cur = ptrs[t * TAGS_ + cur];
        }
    }
}

// =====================================================================
extern "C" void kernel_launch(void* const* d_in, const int* in_sizes, int n_in,
                              void* d_out, int out_size)
{
    const int*   sent  = (const int*)d_in[0];
    const float* mask  = (const float*)d_in[1];
    const float* embed = (const float*)d_in[2];
    const float* Wih_f = (const float*)d_in[3];
    const float* Whh_f = (const float*)d_in[4];
    const float* b_f   = (const float*)d_in[5];
    const float* Wih_b = (const float*)d_in[6];
    const float* Whh_b = (const float*)d_in[7];
    const float* b_b   = (const float*)d_in[8];
    const float* h0f   = (const float*)d_in[9];
    const float* c0f   = (const float*)d_in[10];
    const float* h0b   = (const float*)d_in[11];
    const float* c0b   = (const float*)d_in[12];
    const float* Wtag  = (const float*)d_in[13];
    const float* btag  = (const float*)d_in[14];
    const float* trans = (const float*)d_in[15];

    gx_kernel<<<dim3(T_, 16), 256>>>(sent, embed, Wih_f, b_f, Wih_b, b_b);

    cudaFuncSetAttribute(lstm_kernel, cudaFuncAttributeMaxDynamicSharedMemorySize, LSTM_SMEM);
    lstm_kernel<<<LSTM_NB, 256, LSTM_SMEM>>>(Whh_f, Whh_b, h0f, c0f, h0b, c0b, mask);

    feats_kernel<<<T_, 256>>>(Wtag, btag, mask);

    viterbi_kernel<<<B_, 128>>>(trans, mask, (float*)d_out, out_size);
}